// round 7
// baseline (speedup 1.0000x reference)
#include <cuda_runtime.h>
#include <cstdint>
#include <math.h>

#define NF 64
#define Bn 5000
#define Ln 10
#define Tn 25
#define Kn 8

typedef unsigned long long ull;

// Scratch: u-table [t][b][l][k] (40 MB) so gather rows are contiguous 32B.
__device__ float g_u[(size_t)Tn * Bn * Ln * Kn];

// ---------------------------------------------------------------------------
// Kernel 1: fused cholesky-diag + AR(1) scan, float4-vectorized.
// ---------------------------------------------------------------------------
__global__ void __launch_bounds__(256)
scan_kernel(const float* __restrict__ eps,
            const float* __restrict__ raw_rho,
            const float* __restrict__ Sigma) {
    __shared__ float sA[Kn][Ln * Ln];
    __shared__ float sd[Ln][Kn];

    int tid = threadIdx.x;
    for (int i = tid; i < Kn * Ln * Ln; i += 256)
        ((float*)sA)[i] = Sigma[i];
    __syncthreads();

    if (tid < Kn) {
        float* A = sA[tid];
        for (int i = 0; i < Ln; i++) {
            for (int j = 0; j < i; j++) {
                float s = A[i * Ln + j];
                for (int p = 0; p < j; p++) s -= A[i * Ln + p] * A[j * Ln + p];
                A[i * Ln + j] = __fdividef(s, A[j * Ln + j]);
            }
            float s = A[i * Ln + i];
            for (int p = 0; p < i; p++) s -= A[i * Ln + p] * A[i * Ln + p];
            float dii = sqrtf(s);
            A[i * Ln + i] = dii;
            sd[i][tid] = dii;
        }
    }
    __syncthreads();

    int idx = blockIdx.x * blockDim.x + tid;        // (b, l, kq)
    if (idx >= Bn * Ln * 2) return;
    int kq = idx & 1;
    int l  = (idx >> 1) % Ln;
    int b  = idx / (2 * Ln);

    float4 rr = *(const float4*)(raw_rho + l * Kn + kq * 4);
    float4 rho = make_float4(tanhf(rr.x), tanhf(rr.y), tanhf(rr.z), tanhf(rr.w));
    float4 d = *(float4*)&sd[l][kq * 4];

    const float4* e = (const float4*)(eps + ((size_t)(b * Ln + l) * Tn) * Kn + kq * 4);
    float4* up = (float4*)(g_u + (size_t)(b * Ln + l) * Kn + kq * 4);
    const size_t ustep = (size_t)Bn * Ln * Kn / 4;

    float4 u = __ldcs(&e[0]);
    up[0] = u;
#pragma unroll
    for (int t = 1; t < Tn; t++) {
        float4 ev = __ldcs(&e[t * 2]);
        u.x = fmaf(rho.x, u.x, d.x * ev.x);
        u.y = fmaf(rho.y, u.y, d.y * ev.y);
        u.z = fmaf(rho.z, u.z, d.z * ev.z);
        u.w = fmaf(rho.w, u.w, d.w * ev.w);
        up[(size_t)t * ustep] = u;
    }
}

// ---------------------------------------------------------------------------
// Kernel 2 (persistent, software-pipelined, 3 blocks/SM):
//   out[n,:] = X[n,:] @ beta + u[s,b,l,:]
// Warp = 2 row-slots x 16 chunk-lanes; ONE row per slot per iteration.
// Lane (h,t) loads X float4 chunk t of row g*2+h. beta rows 4t..4t+3 in
// 32 regs, loaded once per warp. Pipeline: X and u one iteration ahead,
// ids two iterations ahead.
// ---------------------------------------------------------------------------
#define FMA2(d_, a_, b_, c_) \
    asm("fma.rn.f32x2 %0, %1, %2, %3;" : "=l"(d_) : "l"(a_), "l"(b_), "l"(c_))
#define ADD2(d_, a_, b_) \
    asm("add.rn.f32x2 %0, %1, %2;" : "=l"(d_) : "l"(a_), "l"(b_))

__device__ __forceinline__ ull dupf(float x) {
    unsigned int w = __float_as_uint(x);
    ull q;
    asm("mov.b64 %0, {%1,%2};" : "=l"(q) : "r"(w), "r"(w));
    return q;
}

// Halving butterfly over 16-lane group: 4 pair-accumulators -> one complete
// pair per lane; lane t ends with pair p = t>>2 on lanes t%4==0.
__device__ __forceinline__ ull reduce16(ull a0, ull a1, ull a2, ull a3, int t) {
    bool hi8 = (t & 8) != 0;
    ull s0 = hi8 ? a0 : a2;
    ull s1 = hi8 ? a1 : a3;
    ull k0 = hi8 ? a2 : a0;
    ull k1 = hi8 ? a3 : a1;
    ull r0 = __shfl_xor_sync(0xffffffffu, s0, 8);
    ull r1 = __shfl_xor_sync(0xffffffffu, s1, 8);
    ADD2(k0, k0, r0);
    ADD2(k1, k1, r1);
    bool hi4 = (t & 4) != 0;
    ull s = hi4 ? k0 : k1;
    ull k = hi4 ? k1 : k0;
    ull rv = __shfl_xor_sync(0xffffffffu, s, 4);
    ADD2(k, k, rv);
    ull rw = __shfl_xor_sync(0xffffffffu, k, 2);
    ADD2(k, k, rw);
    ull rx = __shfl_xor_sync(0xffffffffu, k, 1);
    ADD2(k, k, rx);
    return k;
}

__global__ void __launch_bounds__(256, 3)
main_kernel(const float* __restrict__ X,
            const int* __restrict__ batter_ids,
            const int* __restrict__ league_ids,
            const int* __restrict__ season_ids,
            const float* __restrict__ beta,
            float* __restrict__ out, int N) {
    int lane = threadIdx.x & 31;
    int h    = lane >> 4;            // row slot 0/1
    int t    = lane & 15;            // chunk 0..15
    bool writer = (t & 3) == 0;
    int p = t >> 2;                  // output pair for writer lanes

    // beta rows 4t..4t+3, 4 pairs each -> 16 u64 = 32 regs.
    ull B[4][4];
    const ulonglong2* bp = (const ulonglong2*)beta;
#pragma unroll
    for (int i = 0; i < 4; i++) {
        ulonglong2 lo = __ldg(&bp[(4 * t + i) * 2]);
        ulonglong2 hi = __ldg(&bp[(4 * t + i) * 2 + 1]);
        B[i][0] = lo.x; B[i][1] = lo.y; B[i][2] = hi.x; B[i][3] = hi.y;
    }

    int W  = gridDim.x * (blockDim.x >> 5);                   // total warps
    int gw = blockIdx.x * (blockDim.x >> 5) + (threadIdx.x >> 5);
    int G  = (N + 1) >> 1;                                    // 2-row groups

    // ---- prologue: X[g], ids[g]->u[g], ids[g+W] ----
    int g  = gw;
    int gc = min(g, G - 1);
    int n0 = min(gc * 2 + h, N - 1);
    float4 xc = __ldcs((const float4*)(X + (size_t)n0 * NF) + t);

    int As = 0, Ab = 0, Al = 0;
    float2 uc = make_float2(0.f, 0.f);
    if (writer) {
        int s0 = season_ids[n0], b0 = batter_ids[n0], l0 = league_ids[n0];
        int ga = min(g + W, G - 1);
        int m0 = min(ga * 2 + h, N - 1);
        As = season_ids[m0]; Ab = batter_ids[m0]; Al = league_ids[m0];
        uc = *(const float2*)(g_u + ((size_t)(s0 * Bn + b0) * Ln + l0) * Kn + p * 2);
    }

    while (g < G) {
        int gn = g + W;
        int c1 = min(gn, G - 1);
        int c2 = min(gn + W, G - 1);

        // prefetch X[gn]
        int q0 = min(c1 * 2 + h, N - 1);
        float4 xn = __ldcs((const float4*)(X + (size_t)q0 * NF) + t);

        // prefetch ids[gn+W]; issue u[gn] gather from ids loaded last iter
        int Bs = 0, Bb = 0, Bl = 0;
        float2 un = make_float2(0.f, 0.f);
        if (writer) {
            int m0 = min(c2 * 2 + h, N - 1);
            Bs = season_ids[m0]; Bb = batter_ids[m0]; Bl = league_ids[m0];
            un = *(const float2*)(g_u + ((size_t)(As * Bn + Ab) * Ln + Al) * Kn + p * 2);
        }

        // compute on resident X
        ull a0 = 0, a1 = 0, a2 = 0, a3 = 0;
        float xs[4] = {xc.x, xc.y, xc.z, xc.w};
#pragma unroll
        for (int i = 0; i < 4; i++) {
            ull q = dupf(xs[i]);
            FMA2(a0, q, B[i][0], a0);
            FMA2(a1, q, B[i][1], a1);
            FMA2(a2, q, B[i][2], a2);
            FMA2(a3, q, B[i][3], a3);
        }

        ull K = reduce16(a0, a1, a2, a3, t);

        if (writer) {
            int r = g * 2 + h;
            if (r < N) {
                float f0, f1;
                asm("mov.b64 {%0,%1}, %2;" : "=f"(f0), "=f"(f1) : "l"(K));
                *(float2*)(out + (size_t)r * Kn + p * 2) =
                    make_float2(f0 + uc.x, f1 + uc.y);
            }
        }

        // shift pipeline
        xc = xn;
        uc = un;
        As = Bs; Ab = Bb; Al = Bl;
        g = gn;
    }
}

// ---------------------------------------------------------------------------
extern "C" void kernel_launch(void* const* d_in, const int* in_sizes, int n_in,
                              void* d_out, int out_size) {
    const float* X       = (const float*)d_in[0];
    const int*   bid     = (const int*)d_in[1];
    const int*   lid     = (const int*)d_in[2];
    const int*   sid     = (const int*)d_in[3];
    const float* beta    = (const float*)d_in[4];
    const float* raw_rho = (const float*)d_in[5];
    const float* Sigma   = (const float*)d_in[6];
    const float* eps     = (const float*)d_in[7];
    float*       out     = (float*)d_out;

    const int N = in_sizes[1];

    int chains4 = Bn * Ln * 2;
    scan_kernel<<<(chains4 + 255) / 256, 256>>>(eps, raw_rho, Sigma);

    // Persistent grid: 3 blocks/SM (148 SMs -> 444 blocks).
    main_kernel<<<444, 256>>>(X, bid, lid, sid, beta, out, N);
}

// round 8
// speedup vs baseline: 1.5189x; 1.5189x over previous
#include <cuda_runtime.h>
#include <cstdint>
#include <math.h>

#define NF 64
#define Bn 5000
#define Ln 10
#define Tn 25
#define Kn 8
#define NMAX 1000000

typedef unsigned long long ull;

// Scratch: u-table [t][b][l][k] (40 MB) so gather rows are contiguous 32B.
__device__ float g_u[(size_t)Tn * Bn * Ln * Kn];
// Precomputed gather offsets (element index of the 8-float u row).
__device__ int g_off[NMAX];

// ---------------------------------------------------------------------------
// Kernel 0: u-offset precompute. off[n] = ((s*Bn+b)*Ln+l)*Kn  (max ~10M, int ok)
// ---------------------------------------------------------------------------
__global__ void __launch_bounds__(256)
offs_kernel(const int* __restrict__ sid, const int* __restrict__ bid,
            const int* __restrict__ lid, int N) {
    int n = blockIdx.x * blockDim.x + threadIdx.x;
    if (n < N) g_off[n] = ((sid[n] * Bn + bid[n]) * Ln + lid[n]) * Kn;
}

// ---------------------------------------------------------------------------
// Kernel 1: fused cholesky-diag + AR(1) scan, float4-vectorized.
// ---------------------------------------------------------------------------
__global__ void __launch_bounds__(256)
scan_kernel(const float* __restrict__ eps,
            const float* __restrict__ raw_rho,
            const float* __restrict__ Sigma) {
    __shared__ float sA[Kn][Ln * Ln];
    __shared__ float sd[Ln][Kn];

    int tid = threadIdx.x;
    for (int i = tid; i < Kn * Ln * Ln; i += 256)
        ((float*)sA)[i] = Sigma[i];
    __syncthreads();

    if (tid < Kn) {
        float* A = sA[tid];
        for (int i = 0; i < Ln; i++) {
            for (int j = 0; j < i; j++) {
                float s = A[i * Ln + j];
                for (int p = 0; p < j; p++) s -= A[i * Ln + p] * A[j * Ln + p];
                A[i * Ln + j] = __fdividef(s, A[j * Ln + j]);
            }
            float s = A[i * Ln + i];
            for (int p = 0; p < i; p++) s -= A[i * Ln + p] * A[i * Ln + p];
            float dii = sqrtf(s);
            A[i * Ln + i] = dii;
            sd[i][tid] = dii;
        }
    }
    __syncthreads();

    int idx = blockIdx.x * blockDim.x + tid;        // (b, l, kq)
    if (idx >= Bn * Ln * 2) return;
    int kq = idx & 1;
    int l  = (idx >> 1) % Ln;
    int b  = idx / (2 * Ln);

    float4 rr = *(const float4*)(raw_rho + l * Kn + kq * 4);
    float4 rho = make_float4(tanhf(rr.x), tanhf(rr.y), tanhf(rr.z), tanhf(rr.w));
    float4 d = *(float4*)&sd[l][kq * 4];

    const float4* e = (const float4*)(eps + ((size_t)(b * Ln + l) * Tn) * Kn + kq * 4);
    float4* up = (float4*)(g_u + (size_t)(b * Ln + l) * Kn + kq * 4);
    const size_t ustep = (size_t)Bn * Ln * Kn / 4;

    float4 u = __ldcs(&e[0]);
    up[0] = u;
#pragma unroll
    for (int t = 1; t < Tn; t++) {
        float4 ev = __ldcs(&e[t * 2]);
        u.x = fmaf(rho.x, u.x, d.x * ev.x);
        u.y = fmaf(rho.y, u.y, d.y * ev.y);
        u.z = fmaf(rho.z, u.z, d.z * ev.z);
        u.w = fmaf(rho.w, u.w, d.w * ev.w);
        up[(size_t)t * ustep] = u;
    }
}

// ---------------------------------------------------------------------------
// Kernel 2 (persistent, software-pipelined, 8 rows/warp-iter):
//   out[n,:] = X[n,:] @ beta + u_row[off[n]]
// Warp = 2 row-slots x 16 chunk-lanes; FOUR rows per slot per iteration
// (4 prefetch LDG.128/lane = 2KB outstanding per warp -> 32KB/SM at 16 warps,
// enough MLP to saturate DRAM). beta rows 4t..4t+3 in 32 regs, once/warp.
// Pipeline: X and u one iteration ahead, offsets two iterations ahead.
// ---------------------------------------------------------------------------
#define FMA2(d_, a_, b_, c_) \
    asm("fma.rn.f32x2 %0, %1, %2, %3;" : "=l"(d_) : "l"(a_), "l"(b_), "l"(c_))
#define ADD2(d_, a_, b_) \
    asm("add.rn.f32x2 %0, %1, %2;" : "=l"(d_) : "l"(a_), "l"(b_))

__device__ __forceinline__ ull dupf(float x) {
    unsigned int w = __float_as_uint(x);
    ull q;
    asm("mov.b64 %0, {%1,%2};" : "=l"(q) : "r"(w), "r"(w));
    return q;
}

// Halving butterfly over 16-lane group; lane t ends with pair p = t>>2.
__device__ __forceinline__ ull reduce16(ull a0, ull a1, ull a2, ull a3, int t) {
    bool hi8 = (t & 8) != 0;
    ull s0 = hi8 ? a0 : a2;
    ull s1 = hi8 ? a1 : a3;
    ull k0 = hi8 ? a2 : a0;
    ull k1 = hi8 ? a3 : a1;
    ull r0 = __shfl_xor_sync(0xffffffffu, s0, 8);
    ull r1 = __shfl_xor_sync(0xffffffffu, s1, 8);
    ADD2(k0, k0, r0);
    ADD2(k1, k1, r1);
    bool hi4 = (t & 4) != 0;
    ull s = hi4 ? k0 : k1;
    ull k = hi4 ? k1 : k0;
    ull rv = __shfl_xor_sync(0xffffffffu, s, 4);
    ADD2(k, k, rv);
    ull rw = __shfl_xor_sync(0xffffffffu, k, 2);
    ADD2(k, k, rw);
    ull rx = __shfl_xor_sync(0xffffffffu, k, 1);
    ADD2(k, k, rx);
    return k;
}

__global__ void __launch_bounds__(256, 2)
main_kernel(const float* __restrict__ X,
            const float* __restrict__ beta,
            float* __restrict__ out, int N) {
    int lane = threadIdx.x & 31;
    int h    = lane >> 4;            // row slot 0/1
    int t    = lane & 15;            // chunk 0..15
    bool writer = (t & 3) == 0;
    int p = t >> 2;                  // output pair for writer lanes

    // beta rows 4t..4t+3, 4 pairs each -> 16 u64 = 32 regs.
    ull B[4][4];
    const ulonglong2* bp = (const ulonglong2*)beta;
#pragma unroll
    for (int i = 0; i < 4; i++) {
        ulonglong2 lo = __ldg(&bp[(4 * t + i) * 2]);
        ulonglong2 hi = __ldg(&bp[(4 * t + i) * 2 + 1]);
        B[i][0] = lo.x; B[i][1] = lo.y; B[i][2] = hi.x; B[i][3] = hi.y;
    }

    int W  = gridDim.x * (blockDim.x >> 5);
    int gw = blockIdx.x * (blockDim.x >> 5) + (threadIdx.x >> 5);
    int G  = (N + 7) >> 3;                        // 8-row groups

    int g  = gw;
    int gc = min(g, G - 1);

    // ---- prologue: X[g], u[g] (direct), off[g+W] ----
    float4 xc[4];
#pragma unroll
    for (int j = 0; j < 4; j++) {
        int n = min(gc * 8 + h * 4 + j, N - 1);
        xc[j] = __ldcs((const float4*)(X + (size_t)n * NF) + t);
    }
    int offA[4] = {0, 0, 0, 0};
    float2 uc[4];
#pragma unroll
    for (int j = 0; j < 4; j++) uc[j] = make_float2(0.f, 0.f);
    if (writer) {
        int ga = min(g + W, G - 1);
#pragma unroll
        for (int j = 0; j < 4; j++) {
            int n = min(gc * 8 + h * 4 + j, N - 1);
            uc[j] = *(const float2*)(g_u + g_off[n] + p * 2);
            int m = min(ga * 8 + h * 4 + j, N - 1);
            offA[j] = g_off[m];
        }
    }

    while (g < G) {
        int gn = g + W;
        int c1 = min(gn, G - 1);
        int c2 = min(gn + W, G - 1);

        // prefetch X[gn]  (4 LDG.128 per lane in flight)
        float4 xn[4];
#pragma unroll
        for (int j = 0; j < 4; j++) {
            int n = min(c1 * 8 + h * 4 + j, N - 1);
            xn[j] = __ldcs((const float4*)(X + (size_t)n * NF) + t);
        }

        // prefetch off[gn+W]; gather u[gn] from offsets loaded last iter
        int offB[4] = {0, 0, 0, 0};
        float2 un[4];
#pragma unroll
        for (int j = 0; j < 4; j++) un[j] = make_float2(0.f, 0.f);
        if (writer) {
#pragma unroll
            for (int j = 0; j < 4; j++) {
                int m = min(c2 * 8 + h * 4 + j, N - 1);
                offB[j] = g_off[m];
                un[j] = *(const float2*)(g_u + offA[j] + p * 2);
            }
        }

        // compute 4 row-pairs (both slots in parallel per reduce16)
#pragma unroll
        for (int j = 0; j < 4; j++) {
            ull a0 = 0, a1 = 0, a2 = 0, a3 = 0;
            float xs[4] = {xc[j].x, xc[j].y, xc[j].z, xc[j].w};
#pragma unroll
            for (int i = 0; i < 4; i++) {
                ull q = dupf(xs[i]);
                FMA2(a0, q, B[i][0], a0);
                FMA2(a1, q, B[i][1], a1);
                FMA2(a2, q, B[i][2], a2);
                FMA2(a3, q, B[i][3], a3);
            }
            ull K = reduce16(a0, a1, a2, a3, t);
            if (writer) {
                int r = g * 8 + h * 4 + j;
                if (r < N) {
                    float f0, f1;
                    asm("mov.b64 {%0,%1}, %2;" : "=f"(f0), "=f"(f1) : "l"(K));
                    *(float2*)(out + (size_t)r * Kn + p * 2) =
                        make_float2(f0 + uc[j].x, f1 + uc[j].y);
                }
            }
        }

        // shift pipeline
#pragma unroll
        for (int j = 0; j < 4; j++) {
            xc[j] = xn[j];
            uc[j] = un[j];
            offA[j] = offB[j];
        }
        g = gn;
    }
}

// ---------------------------------------------------------------------------
extern "C" void kernel_launch(void* const* d_in, const int* in_sizes, int n_in,
                              void* d_out, int out_size) {
    const float* X       = (const float*)d_in[0];
    const int*   bid     = (const int*)d_in[1];
    const int*   lid     = (const int*)d_in[2];
    const int*   sid     = (const int*)d_in[3];
    const float* beta    = (const float*)d_in[4];
    const float* raw_rho = (const float*)d_in[5];
    const float* Sigma   = (const float*)d_in[6];
    const float* eps     = (const float*)d_in[7];
    float*       out     = (float*)d_out;

    const int N = in_sizes[1];

    offs_kernel<<<(N + 255) / 256, 256>>>(sid, bid, lid, N);

    int chains4 = Bn * Ln * 2;
    scan_kernel<<<(chains4 + 255) / 256, 256>>>(eps, raw_rho, Sigma);

    // Persistent grid: 2 blocks/SM.
    main_kernel<<<304, 256>>>(X, beta, out, N);
}